// round 1
// baseline (speedup 1.0000x reference)
#include <cuda_runtime.h>
#include <cuda_bf16.h>
#include <cstdint>

#define BSZ   16384
#define DIMC  256
#define DC    128
#define MC    19
#define MD    (MC*DIMC)   /* 4864 */
#define KCAT  384

// ---------------- scratch (device globals; no allocation) ----------------
__device__ __nv_bfloat16 g_feaU[BSZ*DIMC];       // A of GEMM1
__device__ __nv_bfloat16 g_h[BSZ*DC];            // relu output
__device__ __nv_bfloat16 g_feaZ[BSZ*DC];         // fea_z bf16
__device__ __nv_bfloat16 g_W1b[DC*DIMC];
__device__ __nv_bfloat16 g_W2b[DC*DC];
__device__ float         g_b2p[DC];
__device__ __nv_bfloat16 g_Wc[MC*DIMC*KCAT];     // [m][o][384] = [C | WgG]
__device__ float         g_bgp[MC*DIMC];         // bg + WgV@bf
__device__ float         g_part[128*256];        // BN partials: [blk][sum(128)|sumsq(128)]

// ---------------- helpers ----------------
__device__ __forceinline__ uint32_t smem_u32(const void* p) {
    return (uint32_t)__cvta_generic_to_shared(p);
}
__device__ __forceinline__ void cp16(void* dst_smem, const void* src_gmem) {
    uint32_t d = smem_u32(dst_smem);
    asm volatile("cp.async.cg.shared.global [%0], [%1], 16;\n" :: "r"(d), "l"(src_gmem));
}
__device__ __forceinline__ void cp_commit() { asm volatile("cp.async.commit_group;\n"::); }
__device__ __forceinline__ void cp_wait0()  { asm volatile("cp.async.wait_group 0;\n" ::: "memory"); }

__device__ __forceinline__ void ldm_x4(uint32_t& r0, uint32_t& r1, uint32_t& r2, uint32_t& r3,
                                       const void* p) {
    uint32_t a = smem_u32(p);
    asm volatile("ldmatrix.sync.aligned.m8n8.x4.shared.b16 {%0,%1,%2,%3}, [%4];"
                 : "=r"(r0), "=r"(r1), "=r"(r2), "=r"(r3) : "r"(a));
}

// One k16 step of a 32(M) x 64(N) warp tile: 2 m-tiles x 8 n-tiles of m16n8k16.
// sA: row-major [row][k] (lda elems), sB: row-major [n][k] (ldb elems).
__device__ __forceinline__ void mma_step(float (&acc)[2][8][4],
                                         const __nv_bfloat16* sA, int lda, int arow, int acol,
                                         const __nv_bfloat16* sB, int ldb, int nbase, int kcol) {
    const int lane = threadIdx.x & 31;
    uint32_t a[2][4];
#pragma unroll
    for (int mt = 0; mt < 2; mt++) {
        int r = arow + mt*16 + (lane & 7) + ((lane >> 3) & 1) * 8;
        int c = acol + (lane >> 4) * 8;
        ldm_x4(a[mt][0], a[mt][1], a[mt][2], a[mt][3], sA + (size_t)r*lda + c);
    }
    uint32_t b[4][4];
#pragma unroll
    for (int q = 0; q < 4; q++) {
        int n = nbase + q*16 + (lane & 7) + (lane >> 4) * 8;
        int c = kcol + ((lane >> 3) & 1) * 8;
        ldm_x4(b[q][0], b[q][1], b[q][2], b[q][3], sB + (size_t)n*ldb + c);
    }
#pragma unroll
    for (int mt = 0; mt < 2; mt++)
#pragma unroll
        for (int j = 0; j < 8; j++) {
            uint32_t b0 = b[j >> 1][(j & 1) * 2], b1 = b[j >> 1][(j & 1) * 2 + 1];
            asm volatile(
                "mma.sync.aligned.m16n8k16.row.col.f32.bf16.bf16.f32 "
                "{%0,%1,%2,%3},{%4,%5,%6,%7},{%8,%9},{%0,%1,%2,%3};"
                : "+f"(acc[mt][j][0]), "+f"(acc[mt][j][1]), "+f"(acc[mt][j][2]), "+f"(acc[mt][j][3])
                : "r"(a[mt][0]), "r"(a[mt][1]), "r"(a[mt][2]), "r"(a[mt][3]),
                  "r"(b0), "r"(b1));
        }
}

// ---------------- prep kernels ----------------
__global__ void k_prep_w1(const float* __restrict__ W1) {
    int i = blockIdx.x * 256 + threadIdx.x;
    g_W1b[i] = __float2bfloat16(W1[i]);
}

// per-m: C[o][d] = sum_k Wg[m][o][k]*Wf[m][k][d]; Wc = [C | WgG]; bg' = bg + WgV@bf
__global__ void k_prep_wc(const float* __restrict__ Wf, const float* __restrict__ bfv,
                          const float* __restrict__ Wg, const float* __restrict__ bg) {
    extern __shared__ float sWf[];  // 128*128
    const int m = blockIdx.x, tid = threadIdx.x;
    for (int i = tid; i < DC*DC; i += 256) sWf[i] = Wf[(size_t)m*DC*DC + i];
    __syncthreads();
    const float* Wgm = Wg + (size_t)m * DIMC * KCAT;
    for (int i = tid; i < DIMC * KCAT; i += 256) {
        int o = i / KCAT, d = i % KCAT;
        float v;
        if (d < DC) {
            const float* wr = Wgm + (size_t)o * KCAT;
            v = 0.f;
#pragma unroll 8
            for (int k = 0; k < DC; k++) v += wr[k] * sWf[k*DC + d];
        } else {
            v = Wgm[(size_t)o * KCAT + d];
        }
        g_Wc[((size_t)m * DIMC + o) * KCAT + d] = __float2bfloat16(v);
    }
    for (int o = tid; o < DIMC; o += 256) {
        const float* wr = Wgm + (size_t)o * KCAT;
        float v = bg[(size_t)m * DIMC + o];
#pragma unroll 8
        for (int k = 0; k < DC; k++) v += wr[k] * bfv[(size_t)m * DC + k];
        g_bgp[m * DIMC + o] = v;
    }
}

__global__ void k_reduce(const float* __restrict__ x) {
    const int b = blockIdx.x, o = threadIdx.x;
    const float* xp = x + (size_t)b * MD + o;
    float s = 0.f;
#pragma unroll
    for (int m = 0; m < MC; m++) s += xp[m * DIMC];
    g_feaU[b * DIMC + o] = __float2bfloat16(s);
}

// ---------------- small GEMM (M=16384, N=128): SEL 0 -> h=relu(feaU@W1b^T+b1);
//                                               SEL 1 -> feaZ = h@W2b^T + b2p ----------------
template <int KTOT, bool RELU, int SEL>
__global__ __launch_bounds__(256) void k_gemm_small(const float* __restrict__ biasp) {
    __shared__ __nv_bfloat16 sA[2][128 * 40];
    __shared__ __nv_bfloat16 sB[2][128 * 40];
    const __nv_bfloat16* A; const __nv_bfloat16* B; const float* bias; __nv_bfloat16* O;
    if (SEL == 0) { A = g_feaU; B = g_W1b; bias = biasp; O = g_h; }
    else          { A = g_h;    B = g_W2b; bias = g_b2p; O = g_feaZ; }

    const int tid = threadIdx.x, lane = tid & 31, w = tid >> 5;
    const int wm = w >> 1, wn = w & 1;
    const int row0 = blockIdx.x * 128;
    float acc[2][8][4];
#pragma unroll
    for (int a0 = 0; a0 < 2; a0++)
#pragma unroll
        for (int b0 = 0; b0 < 8; b0++)
#pragma unroll
            for (int c0 = 0; c0 < 4; c0++) acc[a0][b0][c0] = 0.f;

    constexpr int NCH = KTOT / 32;
    auto load_chunk = [&](int kb, int buf) {
        for (int i = tid; i < 512; i += 256) {
            int r = i >> 2, seg = i & 3;
            cp16(&sA[buf][r * 40 + seg * 8], A + (size_t)(row0 + r) * KTOT + kb * 32 + seg * 8);
            cp16(&sB[buf][r * 40 + seg * 8], B + (size_t)r * KTOT + kb * 32 + seg * 8);
        }
    };
    load_chunk(0, 0);
    cp_commit();
    for (int kb = 0; kb < NCH; kb++) {
        cp_wait0();
        __syncthreads();
        if (kb + 1 < NCH) { load_chunk(kb + 1, (kb + 1) & 1); cp_commit(); }
        const __nv_bfloat16* cA = sA[kb & 1];
        const __nv_bfloat16* cB = sB[kb & 1];
        mma_step(acc, cA, 40, wm * 32, 0,  cB, 40, wn * 64, 0);
        mma_step(acc, cA, 40, wm * 32, 16, cB, 40, wn * 64, 16);
    }
#pragma unroll
    for (int mt = 0; mt < 2; mt++)
#pragma unroll
        for (int j = 0; j < 8; j++) {
            int rr = row0 + wm * 32 + mt * 16 + (lane >> 2);
            int cc = wn * 64 + j * 8 + (lane & 3) * 2;
            float b0 = bias[cc], b1 = bias[cc + 1];
            float v0 = acc[mt][j][0] + b0, v1 = acc[mt][j][1] + b1;
            float v2 = acc[mt][j][2] + b0, v3 = acc[mt][j][3] + b1;
            if (RELU) { v0 = fmaxf(v0, 0.f); v1 = fmaxf(v1, 0.f); v2 = fmaxf(v2, 0.f); v3 = fmaxf(v3, 0.f); }
            *(__nv_bfloat162*)(O + (size_t)rr * 128 + cc)       = __floats2bfloat162_rn(v0, v1);
            *(__nv_bfloat162*)(O + (size_t)(rr + 8) * 128 + cc) = __floats2bfloat162_rn(v2, v3);
        }
}

// ---------------- BN stats (deterministic two-stage) ----------------
__global__ void k_stats_a() {
    const int j = blockIdx.x, c = threadIdx.x;  // 128 blocks x 128 threads
    const __nv_bfloat16* hp = g_h + (size_t)j * 128 * DC;
    float s = 0.f, q = 0.f;
    for (int r = 0; r < 128; r++) {
        float v = __bfloat162float(hp[r * DC + c]);
        s += v; q += v * v;
    }
    g_part[j * 256 + c] = s;
    g_part[j * 256 + 128 + c] = q;
}

__global__ void k_stats_b(const float* __restrict__ gamma, const float* __restrict__ beta,
                          const float* __restrict__ W2, const float* __restrict__ b2) {
    __shared__ float ssc[128], ssh[128];
    const int c = threadIdx.x;
    float s = 0.f, q = 0.f;
    for (int j = 0; j < 128; j++) { s += g_part[j * 256 + c]; q += g_part[j * 256 + 128 + c]; }
    float mu = s * (1.f / BSZ);
    float var = q * (1.f / BSZ) - mu * mu;
    float sc = gamma[c] * rsqrtf(var + 1e-5f);
    ssc[c] = sc; ssh[c] = beta[c] - mu * sc;
    __syncthreads();
    const int o = c;
    float bb = b2[o];
    for (int k = 0; k < 128; k++) {
        float w = W2[o * 128 + k];
        bb += w * ssh[k];
        g_W2b[o * 128 + k] = __float2bfloat16(w * ssc[k]);
    }
    g_b2p[o] = bb;
}

// ---------------- fused branch attention kernel ----------------
// per CTA: 64 batch rows. smem layout (bytes):
//   sZ  [64][136] bf16     17408
//   sG  [64][264] bf16     33792
//   sW  [2][256][40] bf16  40960
//   sS  [64][260] f32      66560
//   sAc [64][260] f32      66560     total 225280
#define SMEM_BIG 225280

__global__ __launch_bounds__(256) void k_big(const float* __restrict__ x,
                                             const float* __restrict__ g,
                                             float* __restrict__ out) {
    extern __shared__ char smem[];
    __nv_bfloat16* sZ = (__nv_bfloat16*)smem;            // 64*136
    __nv_bfloat16* sG = sZ + 64 * 136;                   // 64*264
    __nv_bfloat16* sW = sG + 64 * 264;                   // 2*256*40
    float* sS  = (float*)(sW + 2 * 256 * 40);            // 64*260
    float* sAc = sS + 64 * 260;                          // 64*260

    const int tid = threadIdx.x, lane = tid & 31, w = tid >> 5;
    const int wm = w >> 2, wn = w & 3;                   // warp grid 2(M) x 4(N)
    const int r0 = blockIdx.x * 64;

    // load fea_z tile (bf16)
    for (int i = tid; i < 1024; i += 256) {
        int r = i >> 4, c8 = i & 15;
        *(uint4*)(sZ + r * 136 + c8 * 8) =
            *(const uint4*)(g_feaZ + (size_t)(r0 + r) * 128 + c8 * 8);
    }
    // zero accum planes
    for (int i = tid; i < 64 * 260; i += 256) { sS[i] = 0.f; sAc[i] = 0.f; }

    for (int m = 0; m < MC; m++) {
        __syncthreads();
        // stage g tile: fp32 -> bf16
        const float* gsrc = g + (size_t)r0 * MD + m * DIMC;
        for (int i = tid; i < 4096; i += 256) {
            int r = i >> 6, c = (i & 63) * 4;
            float4 v = *(const float4*)(gsrc + (size_t)r * MD + c);
            __nv_bfloat162* d = (__nv_bfloat162*)(sG + r * 264 + c);
            d[0] = __floats2bfloat162_rn(v.x, v.y);
            d[1] = __floats2bfloat162_rn(v.z, v.w);
        }
        // first Wc chunk (cp.async)
        {
            const __nv_bfloat16* src = g_Wc + ((size_t)m * DIMC + tid) * KCAT;
#pragma unroll
            for (int s = 0; s < 4; s++) cp16(sW + tid * 40 + s * 8, src + s * 8);
            cp_commit();
        }
        float acc[2][8][4];
#pragma unroll
        for (int a0 = 0; a0 < 2; a0++)
#pragma unroll
            for (int b0 = 0; b0 < 8; b0++)
#pragma unroll
                for (int c0 = 0; c0 < 4; c0++) acc[a0][b0][c0] = 0.f;

        for (int kb = 0; kb < 12; kb++) {
            cp_wait0();
            __syncthreads();
            if (kb < 11) {
                const __nv_bfloat16* src = g_Wc + ((size_t)m * DIMC + tid) * KCAT + (kb + 1) * 32;
                __nv_bfloat16* dst = sW + ((kb + 1) & 1) * (256 * 40) + tid * 40;
#pragma unroll
                for (int s = 0; s < 4; s++) cp16(dst + s * 8, src + s * 8);
                cp_commit();
            }
            const __nv_bfloat16* cB = sW + (kb & 1) * (256 * 40);
            const int kg = kb * 32;
            const __nv_bfloat16* cA; int lda, a0;
            if (kg < 128) { cA = sZ; lda = 136; a0 = kg; }
            else          { cA = sG; lda = 264; a0 = kg - 128; }
            mma_step(acc, cA, lda, wm * 32, a0,      cB, 40, wn * 64, 0);
            mma_step(acc, cA, lda, wm * 32, a0 + 16, cB, 40, wn * 64, 16);
        }
        // epilogue: exp + online accumulate numerator/denominator
        const float* xb  = x + (size_t)r0 * MD + m * DIMC;
        const float* bgm = g_bgp + m * DIMC;
#pragma unroll
        for (int mt = 0; mt < 2; mt++)
#pragma unroll
            for (int j = 0; j < 8; j++) {
                int rr = wm * 32 + mt * 16 + (lane >> 2);
                int cc = wn * 64 + j * 8 + (lane & 3) * 2;
                float bg0 = bgm[cc], bg1 = bgm[cc + 1];
                {
                    float e0 = __expf(acc[mt][j][0] + bg0);
                    float e1 = __expf(acc[mt][j][1] + bg1);
                    float2 xv = *(const float2*)(xb + (size_t)rr * MD + cc);
                    float* ps = sS + rr * 260 + cc;
                    float* pa = sAc + rr * 260 + cc;
                    ps[0] += e0; ps[1] += e1;
                    pa[0] += e0 * xv.x; pa[1] += e1 * xv.y;
                }
                {
                    int r8 = rr + 8;
                    float e0 = __expf(acc[mt][j][2] + bg0);
                    float e1 = __expf(acc[mt][j][3] + bg1);
                    float2 xv = *(const float2*)(xb + (size_t)r8 * MD + cc);
                    float* ps = sS + r8 * 260 + cc;
                    float* pa = sAc + r8 * 260 + cc;
                    ps[0] += e0; ps[1] += e1;
                    pa[0] += e0 * xv.x; pa[1] += e1 * xv.y;
                }
            }
    }
    __syncthreads();
    for (int i = tid; i < 64 * 256; i += 256) {
        int r = i >> 8, c = i & 255;
        out[(size_t)(r0 + r) * 256 + c] = sAc[r * 260 + c] / sS[r * 260 + c];
    }
}

// ---------------- launch ----------------
extern "C" void kernel_launch(void* const* d_in, const int* in_sizes, int n_in,
                              void* d_out, int out_size) {
    const float* x     = (const float*)d_in[0];
    const float* g     = (const float*)d_in[1];
    const float* W1    = (const float*)d_in[2];
    const float* b1    = (const float*)d_in[3];
    const float* gamma = (const float*)d_in[4];
    const float* beta  = (const float*)d_in[5];
    const float* W2    = (const float*)d_in[6];
    const float* b2    = (const float*)d_in[7];
    const float* Wf    = (const float*)d_in[8];
    const float* bfv   = (const float*)d_in[9];
    const float* Wg    = (const float*)d_in[10];
    const float* bg    = (const float*)d_in[11];
    float* out = (float*)d_out;

    cudaFuncSetAttribute(k_prep_wc, cudaFuncAttributeMaxDynamicSharedMemorySize, 64 * 1024);
    cudaFuncSetAttribute(k_big, cudaFuncAttributeMaxDynamicSharedMemorySize, SMEM_BIG);

    k_prep_w1<<<128, 256>>>(W1);
    k_prep_wc<<<MC, 256, 64 * 1024>>>(Wf, bfv, Wg, bg);
    k_reduce<<<BSZ, 256>>>(x);
    k_gemm_small<256, true, 0><<<128, 256>>>(b1);
    k_stats_a<<<128, 128>>>();
    k_stats_b<<<1, 128>>>(gamma, beta, W2, b2);
    k_gemm_small<128, false, 1><<<128, 256>>>(nullptr);
    k_big<<<BSZ / 64, 256, SMEM_BIG>>>(x, g, out);
}

// round 3
// speedup vs baseline: 1.8841x; 1.8841x over previous
#include <cuda_runtime.h>
#include <cuda_bf16.h>
#include <cstdint>

#define BSZ   16384
#define DIMC  256
#define DC    128
#define MC    19
#define MD    (MC*DIMC)   /* 4864 */
#define KCAT  384

// ---------------- scratch (device globals; no allocation) ----------------
__device__ __nv_bfloat16 g_feaU[BSZ*DIMC];
__device__ __nv_bfloat16 g_h[BSZ*DC];
__device__ __nv_bfloat16 g_feaZ[BSZ*DC];
__device__ __nv_bfloat16 g_W1b[DC*DIMC];
__device__ __nv_bfloat16 g_W2b[DC*DC];
__device__ float         g_b2p[DC];
__device__ __nv_bfloat16 g_Wc[MC*DIMC*KCAT];     // [m][o][384] = [C | WgG]
__device__ float         g_bgp[MC*DIMC];         // bg + WgV@bf
__device__ float         g_part[128*256];        // BN partials

// ---------------- helpers ----------------
__device__ __forceinline__ uint32_t smem_u32(const void* p) {
    return (uint32_t)__cvta_generic_to_shared(p);
}
__device__ __forceinline__ void cp16(void* dst_smem, const void* src_gmem) {
    uint32_t d = smem_u32(dst_smem);
    asm volatile("cp.async.cg.shared.global [%0], [%1], 16;\n" :: "r"(d), "l"(src_gmem));
}
__device__ __forceinline__ void cp_commit() { asm volatile("cp.async.commit_group;\n"::); }
__device__ __forceinline__ void cp_wait0()  { asm volatile("cp.async.wait_group 0;\n" ::: "memory"); }

__device__ __forceinline__ void ldm_x4(uint32_t& r0, uint32_t& r1, uint32_t& r2, uint32_t& r3,
                                       const void* p) {
    uint32_t a = smem_u32(p);
    asm volatile("ldmatrix.sync.aligned.m8n8.x4.shared.b16 {%0,%1,%2,%3}, [%4];"
                 : "=r"(r0), "=r"(r1), "=r"(r2), "=r"(r3) : "r"(a));
}

// One k16 step of a 32(M) x 64(N) warp tile: 2 m-tiles x 8 n-tiles of m16n8k16.
__device__ __forceinline__ void mma_step(float (&acc)[2][8][4],
                                         const __nv_bfloat16* sA, int lda, int arow, int acol,
                                         const __nv_bfloat16* sB, int ldb, int nbase, int kcol) {
    const int lane = threadIdx.x & 31;
    uint32_t a[2][4];
#pragma unroll
    for (int mt = 0; mt < 2; mt++) {
        int r = arow + mt*16 + (lane & 7) + ((lane >> 3) & 1) * 8;
        int c = acol + (lane >> 4) * 8;
        ldm_x4(a[mt][0], a[mt][1], a[mt][2], a[mt][3], sA + (size_t)r*lda + c);
    }
    uint32_t b[4][4];
#pragma unroll
    for (int q = 0; q < 4; q++) {
        int n = nbase + q*16 + (lane & 7) + (lane >> 4) * 8;
        int c = kcol + ((lane >> 3) & 1) * 8;
        ldm_x4(b[q][0], b[q][1], b[q][2], b[q][3], sB + (size_t)n*ldb + c);
    }
#pragma unroll
    for (int mt = 0; mt < 2; mt++)
#pragma unroll
        for (int j = 0; j < 8; j++) {
            uint32_t b0 = b[j >> 1][(j & 1) * 2], b1 = b[j >> 1][(j & 1) * 2 + 1];
            asm volatile(
                "mma.sync.aligned.m16n8k16.row.col.f32.bf16.bf16.f32 "
                "{%0,%1,%2,%3},{%4,%5,%6,%7},{%8,%9},{%0,%1,%2,%3};"
                : "+f"(acc[mt][j][0]), "+f"(acc[mt][j][1]), "+f"(acc[mt][j][2]), "+f"(acc[mt][j][3])
                : "r"(a[mt][0]), "r"(a[mt][1]), "r"(a[mt][2]), "r"(a[mt][3]),
                  "r"(b0), "r"(b1));
        }
}

// ---------------- prep kernels ----------------
__global__ void k_prep_w1(const float* __restrict__ W1) {
    int i = blockIdx.x * 256 + threadIdx.x;
    g_W1b[i] = __float2bfloat16(W1[i]);
}

// grid (19,4): block handles m and 64 o-rows.
#define WC_SMEM (128*128*4 + 64*388*4)
__global__ __launch_bounds__(256) void k_prep_wc2(const float* __restrict__ Wf,
                                                  const float* __restrict__ bfv,
                                                  const float* __restrict__ Wg,
                                                  const float* __restrict__ bg) {
    extern __shared__ float ps[];
    float* sWf = ps;                 // [128][128]
    float* sWg = ps + 128 * 128;     // [64][388]
    const int m = blockIdx.x, o0 = blockIdx.y * 64, tid = threadIdx.x;

    const float4* wfsrc = (const float4*)(Wf + (size_t)m * DC * DC);
    for (int i = tid; i < 4096; i += 256) ((float4*)sWf)[i] = wfsrc[i];
    for (int i = tid; i < 6144; i += 256) {
        int o = i / 96, seg = i % 96;
        const float4 v = *(const float4*)(Wg + ((size_t)(m * DIMC + o0 + o)) * KCAT + seg * 4);
        *(float4*)(sWg + o * 388 + seg * 4) = v;
    }
    __syncthreads();

    {
        const int o = tid >> 2, q = tid & 3;
        float c[32];
#pragma unroll
        for (int i = 0; i < 32; i++) c[i] = 0.f;
        const float* wrow = sWg + o * 388;
        for (int k = 0; k < DC; k++) {
            float w = wrow[k];
            const float* fr = sWf + k * DC + q * 32;
#pragma unroll
            for (int i = 0; i < 32; i += 4) {
                float4 f = *(const float4*)(fr + i);
                c[i]   += w * f.x; c[i+1] += w * f.y;
                c[i+2] += w * f.z; c[i+3] += w * f.w;
            }
        }
        __nv_bfloat16* dst = g_Wc + ((size_t)(m * DIMC + o0 + o)) * KCAT + q * 32;
#pragma unroll
        for (int i = 0; i < 32; i += 2)
            *(__nv_bfloat162*)(dst + i) = __floats2bfloat162_rn(c[i], c[i+1]);
    }
    for (int i = tid; i < 64 * 128; i += 256) {
        int o = i >> 7, dd = (i & 127) * 2;
        float2 v = *(const float2*)(sWg + o * 388 + 128 + dd);
        *(__nv_bfloat162*)(g_Wc + ((size_t)(m * DIMC + o0 + o)) * KCAT + 128 + dd) =
            __floats2bfloat162_rn(v.x, v.y);
    }
    if (tid < 64) {
        const int o = tid;
        float bb = bg[(size_t)m * DIMC + o0 + o];
        const float* wrow = sWg + o * 388;
        const float* bp = bfv + (size_t)m * DC;
#pragma unroll 4
        for (int k = 0; k < DC; k++) bb += wrow[k] * bp[k];
        g_bgp[m * DIMC + o0 + o] = bb;
    }
}

__global__ void k_reduce(const float* __restrict__ x) {
    const int b = blockIdx.x, o = threadIdx.x;
    const float* xp = x + (size_t)b * MD + o;
    float s = 0.f;
#pragma unroll
    for (int m = 0; m < MC; m++) s += xp[m * DIMC];
    g_feaU[b * DIMC + o] = __float2bfloat16(s);
}

// ---------------- small GEMMs ----------------
template <int KTOT, bool RELU, int SEL>
__global__ __launch_bounds__(256) void k_gemm_small(const float* __restrict__ biasp) {
    __shared__ __nv_bfloat16 sA[2][128 * 40];
    __shared__ __nv_bfloat16 sB[2][128 * 40];
    const __nv_bfloat16* A; const __nv_bfloat16* B; const float* bias; __nv_bfloat16* O;
    if (SEL == 0) { A = g_feaU; B = g_W1b; bias = biasp; O = g_h; }
    else          { A = g_h;    B = g_W2b; bias = g_b2p; O = g_feaZ; }

    const int tid = threadIdx.x, lane = tid & 31, w = tid >> 5;
    const int wm = w >> 1, wn = w & 1;
    const int row0 = blockIdx.x * 128;
    float acc[2][8][4];
#pragma unroll
    for (int a0 = 0; a0 < 2; a0++)
#pragma unroll
        for (int b0 = 0; b0 < 8; b0++)
#pragma unroll
            for (int c0 = 0; c0 < 4; c0++) acc[a0][b0][c0] = 0.f;

    constexpr int NCH = KTOT / 32;
    auto load_chunk = [&](int kb, int buf) {
        for (int i = tid; i < 512; i += 256) {
            int r = i >> 2, seg = i & 3;
            cp16(&sA[buf][r * 40 + seg * 8], A + (size_t)(row0 + r) * KTOT + kb * 32 + seg * 8);
            cp16(&sB[buf][r * 40 + seg * 8], B + (size_t)r * KTOT + kb * 32 + seg * 8);
        }
    };
    load_chunk(0, 0);
    cp_commit();
    for (int kb = 0; kb < NCH; kb++) {
        cp_wait0();
        __syncthreads();
        if (kb + 1 < NCH) { load_chunk(kb + 1, (kb + 1) & 1); cp_commit(); }
        const __nv_bfloat16* cA = sA[kb & 1];
        const __nv_bfloat16* cB = sB[kb & 1];
        mma_step(acc, cA, 40, wm * 32, 0,  cB, 40, wn * 64, 0);
        mma_step(acc, cA, 40, wm * 32, 16, cB, 40, wn * 64, 16);
    }
#pragma unroll
    for (int mt = 0; mt < 2; mt++)
#pragma unroll
        for (int j = 0; j < 8; j++) {
            int rr = row0 + wm * 32 + mt * 16 + (lane >> 2);
            int cc = wn * 64 + j * 8 + (lane & 3) * 2;
            float b0 = bias[cc], b1 = bias[cc + 1];
            float v0 = acc[mt][j][0] + b0, v1 = acc[mt][j][1] + b1;
            float v2 = acc[mt][j][2] + b0, v3 = acc[mt][j][3] + b1;
            if (RELU) { v0 = fmaxf(v0, 0.f); v1 = fmaxf(v1, 0.f); v2 = fmaxf(v2, 0.f); v3 = fmaxf(v3, 0.f); }
            *(__nv_bfloat162*)(O + (size_t)rr * 128 + cc)       = __floats2bfloat162_rn(v0, v1);
            *(__nv_bfloat162*)(O + (size_t)(rr + 8) * 128 + cc) = __floats2bfloat162_rn(v2, v3);
        }
}

// ---------------- BN stats ----------------
__global__ void k_stats_a() {
    const int j = blockIdx.x, c = threadIdx.x;
    const __nv_bfloat16* hp = g_h + (size_t)j * 128 * DC;
    float s = 0.f, q = 0.f;
    for (int r = 0; r < 128; r++) {
        float v = __bfloat162float(hp[r * DC + c]);
        s += v; q += v * v;
    }
    g_part[j * 256 + c] = s;
    g_part[j * 256 + 128 + c] = q;
}

__global__ void k_stats_b(const float* __restrict__ gamma, const float* __restrict__ beta,
                          const float* __restrict__ W2, const float* __restrict__ b2) {
    __shared__ float ssc[128], ssh[128];
    const int c = threadIdx.x;
    float s = 0.f, q = 0.f;
    for (int j = 0; j < 128; j++) { s += g_part[j * 256 + c]; q += g_part[j * 256 + 128 + c]; }
    float mu = s * (1.f / BSZ);
    float var = q * (1.f / BSZ) - mu * mu;
    float sc = gamma[c] * rsqrtf(var + 1e-5f);
    ssc[c] = sc; ssh[c] = beta[c] - mu * sc;
    __syncthreads();
    const int o = c;
    float bb = b2[o];
    for (int k = 0; k < 128; k++) {
        float w = W2[o * 128 + k];
        bb += w * ssh[k];
        g_W2b[o * 128 + k] = __float2bfloat16(w * ssc[k]);
    }
    g_b2p[o] = bb;
}

// ---------------- fused branch attention (register epilogue) ----------------
// smem: sZ 64x136 bf16 (17408B) + sG 64x264 bf16 (33792B) + sW 2x256x40 bf16 (40960B)
#define SMEM_BIG 92160

__global__ __launch_bounds__(256, 1) void k_big(const float* __restrict__ x,
                                                const float* __restrict__ g,
                                                float* __restrict__ out) {
    extern __shared__ char smem[];
    __nv_bfloat16* sZ = (__nv_bfloat16*)smem;            // 64*136
    __nv_bfloat16* sG = sZ + 64 * 136;                   // 64*264
    __nv_bfloat16* sW = sG + 64 * 264;                   // 2*256*40

    const int tid = threadIdx.x, lane = tid & 31, w = tid >> 5;
    const int wm = w >> 2, wn = w & 3;                   // 2(M) x 4(N) warps
    const int r0 = blockIdx.x * 64;

    // fea_z tile once
    for (int i = tid; i < 1024; i += 256) {
        int r = i >> 4, c8 = i & 15;
        *(uint4*)(sZ + r * 136 + c8 * 8) =
            *(const uint4*)(g_feaZ + (size_t)(r0 + r) * 128 + c8 * 8);
    }

    // register softmax accumulators (fixed (row,col)->thread map across m)
    float eS[2][8][4], eA[2][8][4];
#pragma unroll
    for (int a0 = 0; a0 < 2; a0++)
#pragma unroll
        for (int b0 = 0; b0 < 8; b0++)
#pragma unroll
            for (int c0 = 0; c0 < 4; c0++) { eS[a0][b0][c0] = 0.f; eA[a0][b0][c0] = 0.f; }

    for (int m = 0; m < MC; m++) {
        __syncthreads();   // all warps done with sW/sG of previous m
        // issue Wc chunk 0 (async) before the blocking g stage
        {
            const __nv_bfloat16* src = g_Wc + ((size_t)m * DIMC + tid) * KCAT;
#pragma unroll
            for (int s = 0; s < 4; s++) cp16(sW + tid * 40 + s * 8, src + s * 8);
            cp_commit();
        }
        // stage g tile fp32 -> bf16 (overlaps with chunk-0 cp.async)
        {
            const float* gsrc = g + (size_t)r0 * MD + m * DIMC;
            for (int i = tid; i < 4096; i += 256) {
                int r = i >> 6, c = (i & 63) * 4;
                float4 v = *(const float4*)(gsrc + (size_t)r * MD + c);
                __nv_bfloat162* d = (__nv_bfloat162*)(sG + r * 264 + c);
                d[0] = __floats2bfloat162_rn(v.x, v.y);
                d[1] = __floats2bfloat162_rn(v.z, v.w);
            }
        }
        float acc[2][8][4];
#pragma unroll
        for (int a0 = 0; a0 < 2; a0++)
#pragma unroll
            for (int b0 = 0; b0 < 8; b0++)
#pragma unroll
                for (int c0 = 0; c0 < 4; c0++) acc[a0][b0][c0] = 0.f;

        // Race-free double-buffer pipeline (issue AFTER the barrier):
        // copy of chunk kb+1 still overlaps mma of chunk kb.
        for (int kb = 0; kb < 12; kb++) {
            cp_wait0();
            __syncthreads();
            if (kb < 11) {
                const __nv_bfloat16* src = g_Wc + ((size_t)m * DIMC + tid) * KCAT + (kb + 1) * 32;
                __nv_bfloat16* dst = sW + ((kb + 1) & 1) * (256 * 40) + tid * 40;
#pragma unroll
                for (int s = 0; s < 4; s++) cp16(dst + s * 8, src + s * 8);
                cp_commit();
            }
            const __nv_bfloat16* cB = sW + (kb & 1) * (256 * 40);
            const int kg = kb * 32;
            const __nv_bfloat16* cA; int lda, a0;
            if (kg < 128) { cA = sZ; lda = 136; a0 = kg; }
            else          { cA = sG; lda = 264; a0 = kg - 128; }
            mma_step(acc, cA, lda, wm * 32, a0,      cB, 40, wn * 64, 0);
            mma_step(acc, cA, lda, wm * 32, a0 + 16, cB, 40, wn * 64, 16);
        }

        // register epilogue: exp + accumulate numerator/denominator
        const float* xb  = x + (size_t)r0 * MD + m * DIMC;
        const float* bgm = g_bgp + m * DIMC;
#pragma unroll
        for (int mt = 0; mt < 2; mt++)
#pragma unroll
            for (int j = 0; j < 8; j++) {
                int rr = wm * 32 + mt * 16 + (lane >> 2);
                int cc = wn * 64 + j * 8 + (lane & 3) * 2;
                float bg0 = bgm[cc], bg1 = bgm[cc + 1];
                float2 xv0 = *(const float2*)(xb + (size_t)rr * MD + cc);
                float2 xv1 = *(const float2*)(xb + (size_t)(rr + 8) * MD + cc);
                float e0 = __expf(acc[mt][j][0] + bg0);
                float e1 = __expf(acc[mt][j][1] + bg1);
                float e2 = __expf(acc[mt][j][2] + bg0);
                float e3 = __expf(acc[mt][j][3] + bg1);
                eS[mt][j][0] += e0; eA[mt][j][0] += e0 * xv0.x;
                eS[mt][j][1] += e1; eA[mt][j][1] += e1 * xv0.y;
                eS[mt][j][2] += e2; eA[mt][j][2] += e2 * xv1.x;
                eS[mt][j][3] += e3; eA[mt][j][3] += e3 * xv1.y;
            }
    }

    // final: out = eA / eS, straight from registers
#pragma unroll
    for (int mt = 0; mt < 2; mt++)
#pragma unroll
        for (int j = 0; j < 8; j++) {
            int rr = r0 + wm * 32 + mt * 16 + (lane >> 2);
            int cc = wn * 64 + j * 8 + (lane & 3) * 2;
            float2 o0, o1;
            o0.x = __fdividef(eA[mt][j][0], eS[mt][j][0]);
            o0.y = __fdividef(eA[mt][j][1], eS[mt][j][1]);
            o1.x = __fdividef(eA[mt][j][2], eS[mt][j][2]);
            o1.y = __fdividef(eA[mt][j][3], eS[mt][j][3]);
            *(float2*)(out + (size_t)rr * 256 + cc)       = o0;
            *(float2*)(out + (size_t)(rr + 8) * 256 + cc) = o1;
        }
}

// ---------------- launch ----------------
extern "C" void kernel_launch(void* const* d_in, const int* in_sizes, int n_in,
                              void* d_out, int out_size) {
    const float* x     = (const float*)d_in[0];
    const float* g     = (const float*)d_in[1];
    const float* W1    = (const float*)d_in[2];
    const float* b1    = (const float*)d_in[3];
    const float* gamma = (const float*)d_in[4];
    const float* beta  = (const float*)d_in[5];
    const float* W2    = (const float*)d_in[6];
    const float* b2    = (const float*)d_in[7];
    const float* Wf    = (const float*)d_in[8];
    const float* bfv   = (const float*)d_in[9];
    const float* Wg    = (const float*)d_in[10];
    const float* bg    = (const float*)d_in[11];
    float* out = (float*)d_out;

    cudaFuncSetAttribute(k_prep_wc2, cudaFuncAttributeMaxDynamicSharedMemorySize, WC_SMEM);
    cudaFuncSetAttribute(k_big, cudaFuncAttributeMaxDynamicSharedMemorySize, SMEM_BIG);

    k_prep_w1<<<128, 256>>>(W1);
    k_prep_wc2<<<dim3(MC, 4), 256, WC_SMEM>>>(Wf, bfv, Wg, bg);
    k_reduce<<<BSZ, 256>>>(x);
    k_gemm_small<256, true, 0><<<128, 256>>>(b1);
    k_stats_a<<<128, 128>>>();
    k_stats_b<<<1, 128>>>(gamma, beta, W2, b2);
    k_gemm_small<128, false, 1><<<128, 256>>>(nullptr);
    k_big<<<BSZ / 64, 256, SMEM_BIG>>>(x, g, out);
}